// round 2
// baseline (speedup 1.0000x reference)
#include <cuda_runtime.h>

#define N_NODES 100000
#define N_EDGES 1600000
#define N_GRAPHS 1024
#define HID 32
#define CAP 128
#define EPSN 1e-5f

static_assert((N_NODES * 8) % 256 == 0, "exact grid");
static_assert(N_EDGES % 256 == 0, "exact grid");

// ---------------- scratch (device globals; no allocations allowed) ----------
__device__ int    g_deg[N_NODES];
__device__ int    g_b32[N_NODES];
__device__ float  g_dinv[N_NODES];
__device__ float  g_cnt[N_GRAPHS];
__device__ __align__(16) int g_csr[(size_t)N_NODES * CAP];
__device__ float4 g_h[N_NODES * 8];   // h = x @ W       (as float4 per 4 feats)
__device__ float4 g_a[N_NODES * 8];   // conv output
__device__ float4 g_t[N_NODES * 8];   // graphnorm centered
__device__ float4 g_x[N_NODES * 8];   // layer activations x1/x2/x3
__device__ __align__(16) float g_gs[3][N_GRAPHS * HID];  // per-graph sums
__device__ __align__(16) float g_gv[3][N_GRAPHS * HID];  // per-graph var sums
__device__ __align__(16) float g_pool[N_GRAPHS * HID];   // final pooling sums

// ---------------- helpers ---------------------------------------------------
__device__ __forceinline__ void f4fma(float4& a, float s, float4 v) {
    a.x += s * v.x; a.y += s * v.y; a.z += s * v.z; a.w += s * v.w;
}

__device__ __forceinline__ int clampN(int v) {
    return min(max(v, 0), N_NODES - 1);
}

// Warp-aggregated segment add: layout is (node, f4) with 4 nodes x 8 f4 per warp.
// batch is sorted, so the 4 nodes in a warp usually share a graph id -> reduce
// across node-sublanes first, quartering the L2 atomic count.
__device__ __forceinline__ void seg_add(float* base, int g, float4 v) {
    unsigned lane = threadIdx.x & 31u;
    int g0 = __shfl_sync(0xffffffffu, g, lane & 7u);
    if (__all_sync(0xffffffffu, g == g0)) {
        v.x += __shfl_xor_sync(0xffffffffu, v.x, 8);
        v.y += __shfl_xor_sync(0xffffffffu, v.y, 8);
        v.z += __shfl_xor_sync(0xffffffffu, v.z, 8);
        v.w += __shfl_xor_sync(0xffffffffu, v.w, 8);
        v.x += __shfl_xor_sync(0xffffffffu, v.x, 16);
        v.y += __shfl_xor_sync(0xffffffffu, v.y, 16);
        v.z += __shfl_xor_sync(0xffffffffu, v.z, 16);
        v.w += __shfl_xor_sync(0xffffffffu, v.w, 16);
        if (lane < 8) {
            float* p = base + (size_t)g * HID + lane * 4;
            atomicAdd(p + 0, v.x); atomicAdd(p + 1, v.y);
            atomicAdd(p + 2, v.z); atomicAdd(p + 3, v.w);
        }
    } else {
        float* p = base + (size_t)g * HID + (lane & 7u) * 4;
        atomicAdd(p + 0, v.x); atomicAdd(p + 1, v.y);
        atomicAdd(p + 2, v.z); atomicAdd(p + 3, v.w);
    }
}

// ---------------- setup kernels --------------------------------------------
__global__ void k_zero() {
    int i = blockIdx.x * blockDim.x + threadIdx.x;
    if (i < N_NODES) g_deg[i] = 0;
    if (i < N_GRAPHS) g_cnt[i] = 0.0f;
    if (i < N_GRAPHS * HID) {
        g_gs[0][i] = 0.0f; g_gs[1][i] = 0.0f; g_gs[2][i] = 0.0f;
        g_gv[0][i] = 0.0f; g_gv[1][i] = 0.0f; g_gv[2][i] = 0.0f;
        g_pool[i] = 0.0f;
    }
}

__global__ void k_batch(const int* __restrict__ batch) {
    int i = blockIdx.x * blockDim.x + threadIdx.x;
    if (i >= N_NODES) return;
    int b = min(max(batch[i], 0), N_GRAPHS - 1);
    g_b32[i] = b;
    atomicAdd(&g_cnt[b], 1.0f);
}

// Single-pass padded-CSR build: histogram + fill (no prefix sum needed).
__global__ void k_edges(const int* __restrict__ ei) {
    int e = blockIdx.x * blockDim.x + threadIdx.x;
    if (e >= N_EDGES) return;
    int r = clampN(ei[e]);
    int c = clampN(ei[N_EDGES + e]);
    int s = atomicAdd(&g_deg[c], 1);
    if (s < CAP) g_csr[(size_t)c * CAP + s] = r;
}

__global__ void k_dinv() {
    int i = blockIdx.x * blockDim.x + threadIdx.x;
    if (i >= N_NODES) return;
    g_dinv[i] = rsqrtf((float)(g_deg[i] + 1));  // +1 self-loop
}

// ---------------- dense projections ----------------------------------------
__global__ void k_h3(const float* __restrict__ x, const float* __restrict__ W) {
    int t = blockIdx.x * blockDim.x + threadIdx.x;   // exact grid: N*8 threads
    int n = t >> 3, f4 = t & 7;
    float x0 = x[n * 3 + 0], x1 = x[n * 3 + 1], x2 = x[n * 3 + 2];
    const float4* W4 = (const float4*)W;             // [3][8] float4
    float4 h = make_float4(0.f, 0.f, 0.f, 0.f);
    f4fma(h, x0, W4[0 * 8 + f4]);
    f4fma(h, x1, W4[1 * 8 + f4]);
    f4fma(h, x2, W4[2 * 8 + f4]);
    g_h[t] = h;
}

__global__ void k_h32(const float* __restrict__ W) {
    __shared__ float4 sw[32 * 8];
    int tid = threadIdx.x;                           // blockDim must be 256
    sw[tid] = ((const float4*)W)[tid];
    __syncthreads();
    int t = blockIdx.x * 256 + tid;                  // exact grid
    int n = t >> 3, f4 = t & 7;
    const float4* xr = &g_x[n * 8];
    float4 acc = make_float4(0.f, 0.f, 0.f, 0.f);
#pragma unroll
    for (int k4 = 0; k4 < 8; k4++) {
        float4 xv = xr[k4];
        f4fma(acc, xv.x, sw[(k4 * 4 + 0) * 8 + f4]);
        f4fma(acc, xv.y, sw[(k4 * 4 + 1) * 8 + f4]);
        f4fma(acc, xv.z, sw[(k4 * 4 + 2) * 8 + f4]);
        f4fma(acc, xv.w, sw[(k4 * 4 + 3) * 8 + f4]);
    }
    g_h[t] = acc;
}

// ---------------- GCN gather (the hot kernel) + fused per-graph sum ---------
__global__ void k_gather(const float* __restrict__ bias, int L) {
    int t = blockIdx.x * blockDim.x + threadIdx.x;   // exact grid: N*8
    int n = t >> 3, f4 = t & 7;
    float di = g_dinv[n];
    int d = min(g_deg[n], CAP);
    const int* cp = g_csr + (size_t)n * CAP;
    float4 acc = make_float4(0.f, 0.f, 0.f, 0.f);
    int e = 0;
    for (; e + 4 <= d; e += 4) {
        int4 rr = *(const int4*)(cp + e);            // 16B-aligned (e%4==0)
        float w0 = g_dinv[rr.x], w1 = g_dinv[rr.y];
        float w2 = g_dinv[rr.z], w3 = g_dinv[rr.w];
        float4 h0 = g_h[rr.x * 8 + f4];
        float4 h1 = g_h[rr.y * 8 + f4];
        float4 h2 = g_h[rr.z * 8 + f4];
        float4 h3 = g_h[rr.w * 8 + f4];
        f4fma(acc, w0, h0); f4fma(acc, w1, h1);
        f4fma(acc, w2, h2); f4fma(acc, w3, h3);
    }
    for (; e < d; e++) {
        int r = cp[e];
        f4fma(acc, g_dinv[r], g_h[r * 8 + f4]);
    }
    float4 hs = g_h[t];
    float4 b4 = ((const float4*)bias)[f4];
    float4 out;
    out.x = b4.x + di * (di * hs.x + acc.x);
    out.y = b4.y + di * (di * hs.y + acc.y);
    out.z = b4.z + di * (di * hs.z + acc.z);
    out.w = b4.w + di * (di * hs.w + acc.w);
    g_a[t] = out;
    seg_add(g_gs[L], g_b32[n], out);                 // fused graph-sum for GN mean
}

// ---------------- GraphNorm: center (+ fused var accumulation) --------------
__global__ void k_t(const float* __restrict__ ms, int L) {
    int t = blockIdx.x * blockDim.x + threadIdx.x;   // exact grid
    int n = t >> 3, f4 = t & 7;
    int g = g_b32[n];
    float rc = 1.0f / fmaxf(g_cnt[g], 1.0f);
    float4 m = ((const float4*)(g_gs[L] + (size_t)g * HID))[f4];
    float4 s = ((const float4*)ms)[f4];
    float4 a = g_a[t];
    float4 tv;
    tv.x = a.x - m.x * rc * s.x;
    tv.y = a.y - m.y * rc * s.y;
    tv.z = a.z - m.z * rc * s.z;
    tv.w = a.w - m.w * rc * s.w;
    g_t[t] = tv;
    float4 sq = make_float4(tv.x * tv.x, tv.y * tv.y, tv.z * tv.z, tv.w * tv.w);
    seg_add(g_gv[L], g, sq);                         // fused var-sum
}

// ---------------- GraphNorm: scale + (residual, relu, optional pooling) -----
template <int RES, int POOL>
__global__ void k_y(const float* __restrict__ w, const float* __restrict__ be, int L) {
    int t = blockIdx.x * blockDim.x + threadIdx.x;   // exact grid
    int n = t >> 3, f4 = t & 7;
    int g = g_b32[n];
    float rc = 1.0f / fmaxf(g_cnt[g], 1.0f);
    float4 v = ((const float4*)(g_gv[L] + (size_t)g * HID))[f4];
    float4 w4 = ((const float4*)w)[f4];
    float4 b4 = ((const float4*)be)[f4];
    float4 tv = g_t[t];
    float4 y;
    y.x = w4.x * tv.x * rsqrtf(v.x * rc + EPSN) + b4.x;
    y.y = w4.y * tv.y * rsqrtf(v.y * rc + EPSN) + b4.y;
    y.z = w4.z * tv.z * rsqrtf(v.z * rc + EPSN) + b4.z;
    y.w = w4.w * tv.w * rsqrtf(v.w * rc + EPSN) + b4.w;
    if (RES) {
        float4 xo = g_x[t];
        y.x += xo.x; y.y += xo.y; y.z += xo.z; y.w += xo.w;
    }
    y.x = fmaxf(y.x, 0.f); y.y = fmaxf(y.y, 0.f);
    y.z = fmaxf(y.z, 0.f); y.w = fmaxf(y.w, 0.f);
    g_x[t] = y;
    if (POOL) seg_add(g_pool, g, y);                 // fused global mean-pool sum
}

// ---------------- head ------------------------------------------------------
__global__ void k_final(const float* __restrict__ Wl, const float* __restrict__ bl,
                        float* __restrict__ out) {
    int i = blockIdx.x * blockDim.x + threadIdx.x;
    if (i >= N_GRAPHS * 3) return;
    int g = i / 3, j = i % 3;
    float rc = 1.0f / fmaxf(g_cnt[g], 1.0f);
    const float* pr = g_pool + (size_t)g * HID;
    float acc = bl[j];
#pragma unroll
    for (int f = 0; f < HID; f++) acc += pr[f] * rc * Wl[f * 3 + j];
    out[i] = acc;
}

// ---------------- launch -----------------------------------------------------
extern "C" void kernel_launch(void* const* d_in, const int* in_sizes, int n_in,
                              void* d_out, int out_size) {
    const float* x     = (const float*)d_in[0];
    const int*   ei    = (const int*)d_in[1];     // int32 (JAX x64 disabled)
    const int*   batch = (const int*)d_in[2];     // int32
    const float* W1 = (const float*)d_in[3];
    const float* b1 = (const float*)d_in[4];
    const float* W2 = (const float*)d_in[5];
    const float* b2 = (const float*)d_in[6];
    const float* W3 = (const float*)d_in[7];
    const float* b3 = (const float*)d_in[8];
    const float* g1 = (const float*)d_in[9];
    const float* be1 = (const float*)d_in[10];
    const float* ms1 = (const float*)d_in[11];
    const float* g2 = (const float*)d_in[12];
    const float* be2 = (const float*)d_in[13];
    const float* ms2 = (const float*)d_in[14];
    const float* g3 = (const float*)d_in[15];
    const float* be3 = (const float*)d_in[16];
    const float* ms3 = (const float*)d_in[17];
    const float* Wl = (const float*)d_in[18];
    const float* bl = (const float*)d_in[19];
    float* out = (float*)d_out;

    const int TB = 256;
    const int GN  = (N_NODES + TB - 1) / TB;   // 391
    const int GE  = N_EDGES / TB;              // 6250 (exact)
    const int GF  = (N_NODES * 8) / TB;        // 3125 (exact)
    const int GO  = (N_GRAPHS * 3 + TB - 1) / TB;

    k_zero<<<GN, TB>>>();
    k_edges<<<GE, TB>>>(ei);
    k_batch<<<GN, TB>>>(batch);
    k_dinv<<<GN, TB>>>();

    // layer 1
    k_h3<<<GF, TB>>>(x, W1);
    k_gather<<<GF, TB>>>(b1, 0);
    k_t<<<GF, TB>>>(ms1, 0);
    k_y<0, 0><<<GF, TB>>>(g1, be1, 0);

    // layer 2 (residual)
    k_h32<<<GF, TB>>>(W2);
    k_gather<<<GF, TB>>>(b2, 1);
    k_t<<<GF, TB>>>(ms2, 1);
    k_y<1, 0><<<GF, TB>>>(g2, be2, 1);

    // layer 3 (residual + pooling)
    k_h32<<<GF, TB>>>(W3);
    k_gather<<<GF, TB>>>(b3, 2);
    k_t<<<GF, TB>>>(ms3, 2);
    k_y<1, 1><<<GF, TB>>>(g3, be3, 2);

    k_final<<<GO, TB>>>(Wl, bl, out);
}

// round 3
// speedup vs baseline: 1.2574x; 1.2574x over previous
#include <cuda_runtime.h>
#include <cuda_fp16.h>

#define N_NODES 100000
#define N_EDGES 1600000
#define N_GRAPHS 1024
#define HID 32
#define CAP 128
#define EPSN 1e-5f

static_assert((N_NODES * 8) % 256 == 0, "exact grid");
static_assert(N_EDGES % 4 == 0, "edge vec");

// ---------------- scratch (device globals; no allocations allowed) ----------
__device__ int    g_deg[N_NODES];
__device__ int    g_b32[N_NODES];
__device__ float  g_dinv[N_NODES];
__device__ float  g_cnt[N_GRAPHS];
__device__ __align__(16)  int   g_csr[(size_t)N_NODES * CAP];
__device__ __align__(128) uint2 g_hq[N_NODES * 8];   // hs = dinv*(x@W), 4 halves/entry
__device__ float4 g_a[N_NODES * 8];                  // conv output (fp32)
__device__ float4 g_x[N_NODES * 8];                  // layer activations x1/x2
__device__ __align__(16) float g_gs[3][N_GRAPHS * HID];  // per-graph sums
__device__ __align__(16) float g_gv[3][N_GRAPHS * HID];  // per-graph sum-of-squares
__device__ __align__(16) float g_pool[N_GRAPHS * HID];   // pooling sums

// ---------------- helpers ---------------------------------------------------
__device__ __forceinline__ void f4fma(float4& a, float s, float4 v) {
    a.x += s * v.x; a.y += s * v.y; a.z += s * v.z; a.w += s * v.w;
}
__device__ __forceinline__ void f4add(float4& a, float4 v) {
    a.x += v.x; a.y += v.y; a.z += v.z; a.w += v.w;
}
__device__ __forceinline__ int clampN(int v) { return min(max(v, 0), N_NODES - 1); }

__device__ __forceinline__ float4 unpack_h(uint2 q) {
    __half2 lo = *(__half2*)&q.x, hi = *(__half2*)&q.y;
    float2 a = __half22float2(lo), b = __half22float2(hi);
    return make_float4(a.x, a.y, b.x, b.y);
}
__device__ __forceinline__ uint2 pack_h(float4 v) {
    __half2 lo = __floats2half2_rn(v.x, v.y);
    __half2 hi = __floats2half2_rn(v.z, v.w);
    uint2 q; q.x = *(unsigned*)&lo; q.y = *(unsigned*)&hi; return q;
}

__device__ __forceinline__ void red4(float4& v) {
    v.x += __shfl_xor_sync(0xffffffffu, v.x, 8);
    v.y += __shfl_xor_sync(0xffffffffu, v.y, 8);
    v.z += __shfl_xor_sync(0xffffffffu, v.z, 8);
    v.w += __shfl_xor_sync(0xffffffffu, v.w, 8);
    v.x += __shfl_xor_sync(0xffffffffu, v.x, 16);
    v.y += __shfl_xor_sync(0xffffffffu, v.y, 16);
    v.z += __shfl_xor_sync(0xffffffffu, v.z, 16);
    v.w += __shfl_xor_sync(0xffffffffu, v.w, 16);
}
__device__ __forceinline__ void at4(float* p, float4 v) {
    atomicAdd(p + 0, v.x); atomicAdd(p + 1, v.y);
    atomicAdd(p + 2, v.z); atomicAdd(p + 3, v.w);
}

// Warp-aggregated segment add (single payload). Layout: 4 nodes x 8 f4 per warp.
__device__ __forceinline__ void seg_add(float* base, int g, float4 v) {
    unsigned lane = threadIdx.x & 31u;
    int g0 = __shfl_sync(0xffffffffu, g, 0);
    if (__all_sync(0xffffffffu, g == g0)) {
        red4(v);
        if (lane < 8) at4(base + (size_t)g * HID + lane * 4, v);
    } else {
        at4(base + (size_t)g * HID + (lane & 7u) * 4, v);
    }
}

// Dual payload: lanes 0-7 flush A, lanes 8-15 flush B after cross-node reduce.
__device__ __forceinline__ void seg_add2(float* baseA, float* baseB, int g,
                                         float4 va, float4 vb) {
    unsigned lane = threadIdx.x & 31u;
    int g0 = __shfl_sync(0xffffffffu, g, 0);
    if (__all_sync(0xffffffffu, g == g0)) {
        red4(va); red4(vb);
        if (lane < 8)       at4(baseA + (size_t)g * HID + lane * 4, va);
        else if (lane < 16) at4(baseB + (size_t)g * HID + (lane - 8) * 4, vb);
    } else {
        unsigned f4 = lane & 7u;
        at4(baseA + (size_t)g * HID + f4 * 4, va);
        at4(baseB + (size_t)g * HID + f4 * 4, vb);
    }
}

// ---------------- setup kernels --------------------------------------------
__global__ void k_zero() {
    int i = blockIdx.x * blockDim.x + threadIdx.x;
    if (i < N_NODES) g_deg[i] = 0;
    if (i < N_GRAPHS) g_cnt[i] = 0.0f;
    if (i < N_GRAPHS * HID) {
        g_gs[0][i] = 0.0f; g_gs[1][i] = 0.0f; g_gs[2][i] = 0.0f;
        g_gv[0][i] = 0.0f; g_gv[1][i] = 0.0f; g_gv[2][i] = 0.0f;
        g_pool[i] = 0.0f;
    }
}

// 4 edges per thread, int4-vectorized index loads.
__global__ void k_edges(const int* __restrict__ ei) {
    int i = blockIdx.x * blockDim.x + threadIdx.x;
    int e = i * 4;
    if (e >= N_EDGES) return;
    int4 r = *(const int4*)(ei + e);
    int4 c = *(const int4*)(ei + N_EDGES + e);
#pragma unroll
    for (int j = 0; j < 4; j++) {
        int rr = clampN(j == 0 ? r.x : j == 1 ? r.y : j == 2 ? r.z : r.w);
        int cc = clampN(j == 0 ? c.x : j == 1 ? c.y : j == 2 ? c.z : c.w);
        int s = atomicAdd(&g_deg[cc], 1);
        if (s < CAP) g_csr[(size_t)cc * CAP + s] = rr;
    }
}

// batch decode + counts + dinv (after k_edges).
__global__ void k_bd(const int* __restrict__ batch) {
    int i = blockIdx.x * blockDim.x + threadIdx.x;
    if (i >= N_NODES) return;
    int b = min(max(batch[i], 0), N_GRAPHS - 1);
    g_b32[i] = b;
    atomicAdd(&g_cnt[b], 1.0f);
    g_dinv[i] = rsqrtf((float)(g_deg[i] + 1));  // +1 self-loop
}

// ---------------- layer-1 projection: hs = dinv * (x @ W1) ------------------
__global__ void k_h3(const float* __restrict__ x, const float* __restrict__ W) {
    int t = blockIdx.x * blockDim.x + threadIdx.x;   // exact grid: N*8
    int n = t >> 3, f4 = t & 7;
    float x0 = x[n * 3 + 0], x1 = x[n * 3 + 1], x2 = x[n * 3 + 2];
    const float4* W4 = (const float4*)W;             // [3][8] float4
    float4 h = make_float4(0.f, 0.f, 0.f, 0.f);
    f4fma(h, x0, W4[0 * 8 + f4]);
    f4fma(h, x1, W4[1 * 8 + f4]);
    f4fma(h, x2, W4[2 * 8 + f4]);
    float di = g_dinv[n];
    h.x *= di; h.y *= di; h.z *= di; h.w *= di;
    g_hq[t] = pack_h(h);
}

// ---------------- GCN gather + fused per-graph sum / sumsq ------------------
__global__ void k_gather(const float* __restrict__ bias, int L) {
    int t = blockIdx.x * blockDim.x + threadIdx.x;   // exact grid: N*8
    int n = t >> 3, f4 = t & 7;
    float di = g_dinv[n];
    int d = min(g_deg[n], CAP);
    const int* cp = g_csr + (size_t)n * CAP;
    float4 acc = unpack_h(g_hq[t]);                  // self-loop term
    int e = 0;
    for (; e + 4 <= d; e += 4) {
        int4 rr = *(const int4*)(cp + e);
        uint2 q0 = g_hq[rr.x * 8 + f4];
        uint2 q1 = g_hq[rr.y * 8 + f4];
        uint2 q2 = g_hq[rr.z * 8 + f4];
        uint2 q3 = g_hq[rr.w * 8 + f4];
        f4add(acc, unpack_h(q0)); f4add(acc, unpack_h(q1));
        f4add(acc, unpack_h(q2)); f4add(acc, unpack_h(q3));
    }
    for (; e < d; e++) f4add(acc, unpack_h(g_hq[cp[e] * 8 + f4]));
    float4 b4 = ((const float4*)bias)[f4];
    float4 out;
    out.x = b4.x + di * acc.x;
    out.y = b4.y + di * acc.y;
    out.z = b4.z + di * acc.z;
    out.w = b4.w + di * acc.w;
    g_a[t] = out;
    float4 sq = make_float4(out.x * out.x, out.y * out.y, out.z * out.z, out.w * out.w);
    seg_add2(g_gs[L], g_gv[L], g_b32[n], out, sq);   // fused mean + var sums
}

// ------- GraphNorm(scale) + residual + relu + {next x@W | pooling} ----------
// var = SS/c - 2*s*mean + s^2, s = mean*ms  (removes the separate center pass)
template <int RES, int POOL, int NEXTW>
__global__ void k_y(const float* __restrict__ w, const float* __restrict__ be,
                    const float* __restrict__ ms, const float* __restrict__ Wn, int L) {
    __shared__ float4 sw[32 * 8];
    int tid = threadIdx.x;                           // blockDim must be 256
    if (NEXTW) { sw[tid] = ((const float4*)Wn)[tid]; __syncthreads(); }
    int t = blockIdx.x * 256 + tid;                  // exact grid
    int n = t >> 3, f4 = t & 7;
    int g = g_b32[n];
    float rc = 1.0f / fmaxf(g_cnt[g], 1.0f);
    float4 S  = ((const float4*)(g_gs[L] + (size_t)g * HID))[f4];
    float4 SS = ((const float4*)(g_gv[L] + (size_t)g * HID))[f4];
    float4 mv = ((const float4*)ms)[f4];
    float4 w4 = ((const float4*)w)[f4];
    float4 b4 = ((const float4*)be)[f4];
    float4 a = g_a[t];
    float4 y;
    {
        float mean, s, var;
        mean = S.x * rc; s = mean * mv.x; var = SS.x * rc - 2.f * s * mean + s * s;
        y.x = w4.x * (a.x - s) * rsqrtf(var + EPSN) + b4.x;
        mean = S.y * rc; s = mean * mv.y; var = SS.y * rc - 2.f * s * mean + s * s;
        y.y = w4.y * (a.y - s) * rsqrtf(var + EPSN) + b4.y;
        mean = S.z * rc; s = mean * mv.z; var = SS.z * rc - 2.f * s * mean + s * s;
        y.z = w4.z * (a.z - s) * rsqrtf(var + EPSN) + b4.z;
        mean = S.w * rc; s = mean * mv.w; var = SS.w * rc - 2.f * s * mean + s * s;
        y.w = w4.w * (a.w - s) * rsqrtf(var + EPSN) + b4.w;
    }
    if (RES) {
        float4 xo = g_x[t];
        y.x += xo.x; y.y += xo.y; y.z += xo.z; y.w += xo.w;
    }
    y.x = fmaxf(y.x, 0.f); y.y = fmaxf(y.y, 0.f);
    y.z = fmaxf(y.z, 0.f); y.w = fmaxf(y.w, 0.f);
    if (POOL) {
        seg_add(g_pool, g, y);                       // final layer: only pooling consumes y
    } else {
        g_x[t] = y;                                  // keep for next residual
    }
    if (NEXTW) {
        // next-layer projection via intra-node warp shuffles: h = y @ Wn
        unsigned lane = tid & 31u, base = lane & ~7u;
        float4 acc = make_float4(0.f, 0.f, 0.f, 0.f);
#pragma unroll
        for (int j = 0; j < 8; j++) {
            float yx = __shfl_sync(0xffffffffu, y.x, base + j);
            float yy = __shfl_sync(0xffffffffu, y.y, base + j);
            float yz = __shfl_sync(0xffffffffu, y.z, base + j);
            float yw = __shfl_sync(0xffffffffu, y.w, base + j);
            f4fma(acc, yx, sw[(j * 4 + 0) * 8 + f4]);
            f4fma(acc, yy, sw[(j * 4 + 1) * 8 + f4]);
            f4fma(acc, yz, sw[(j * 4 + 2) * 8 + f4]);
            f4fma(acc, yw, sw[(j * 4 + 3) * 8 + f4]);
        }
        float di = g_dinv[n];
        acc.x *= di; acc.y *= di; acc.z *= di; acc.w *= di;
        g_hq[t] = pack_h(acc);
    }
}

// ---------------- head ------------------------------------------------------
__global__ void k_final(const float* __restrict__ Wl, const float* __restrict__ bl,
                        float* __restrict__ out) {
    int i = blockIdx.x * blockDim.x + threadIdx.x;
    if (i >= N_GRAPHS * 3) return;
    int g = i / 3, j = i % 3;
    float rc = 1.0f / fmaxf(g_cnt[g], 1.0f);
    const float* pr = g_pool + (size_t)g * HID;
    float acc = bl[j];
#pragma unroll
    for (int f = 0; f < HID; f++) acc += pr[f] * rc * Wl[f * 3 + j];
    out[i] = acc;
}

// ---------------- launch -----------------------------------------------------
extern "C" void kernel_launch(void* const* d_in, const int* in_sizes, int n_in,
                              void* d_out, int out_size) {
    const float* x     = (const float*)d_in[0];
    const int*   ei    = (const int*)d_in[1];     // int32 (JAX x64 disabled)
    const int*   batch = (const int*)d_in[2];     // int32
    const float* W1 = (const float*)d_in[3];
    const float* b1 = (const float*)d_in[4];
    const float* W2 = (const float*)d_in[5];
    const float* b2 = (const float*)d_in[6];
    const float* W3 = (const float*)d_in[7];
    const float* b3 = (const float*)d_in[8];
    const float* g1 = (const float*)d_in[9];
    const float* be1 = (const float*)d_in[10];
    const float* ms1 = (const float*)d_in[11];
    const float* g2 = (const float*)d_in[12];
    const float* be2 = (const float*)d_in[13];
    const float* ms2 = (const float*)d_in[14];
    const float* g3 = (const float*)d_in[15];
    const float* be3 = (const float*)d_in[16];
    const float* ms3 = (const float*)d_in[17];
    const float* Wl = (const float*)d_in[18];
    const float* bl = (const float*)d_in[19];
    float* out = (float*)d_out;

    const int TB = 256;
    const int GN  = (N_NODES + TB - 1) / TB;        // 391
    const int GE  = (N_EDGES / 4 + TB - 1) / TB;    // 1563
    const int GF  = (N_NODES * 8) / TB;             // 3125 (exact)
    const int GO  = (N_GRAPHS * 3 + TB - 1) / TB;

    k_zero<<<GN, TB>>>();
    k_edges<<<GE, TB>>>(ei);
    k_bd<<<GN, TB>>>(batch);

    k_h3<<<GF, TB>>>(x, W1);
    k_gather<<<GF, TB>>>(b1, 0);
    k_y<0, 0, 1><<<GF, TB>>>(g1, be1, ms1, W2, 0);  // gn+relu, emit h2

    k_gather<<<GF, TB>>>(b2, 1);
    k_y<1, 0, 1><<<GF, TB>>>(g2, be2, ms2, W3, 1);  // gn+res+relu, emit h3

    k_gather<<<GF, TB>>>(b3, 2);
    k_y<1, 1, 0><<<GF, TB>>>(g3, be3, ms3, W3, 2);  // gn+res+relu, pool

    k_final<<<GO, TB>>>(Wl, bl, out);
}